// round 10
// baseline (speedup 1.0000x reference)
#include <cuda_runtime.h>
#include <cstdint>

// BoundingBox: mask [N,1,H,W] fp32 -> bbox [N,4] float32 (ymin, xmin, ymax, xmax),
// hit = (v >= 0.5f). Reference: lo = first hit, hi = last hit + 1; no hit -> (0, full).
//
// FINAL. Twice-verified best (4.544us r5, 4.608us r9 harness; ~4.2-4.3us ncu).
// Structure: one block per image, 4 warps, one direction per warp, 32-element
// ballot-batched early-exit scans. Expected 1 batch per direction on dense random
// masks -> ~1MB traffic instead of 134MB (126x cut); kernel sits on the launch-
// overhead + one-DRAM-round-trip floor (every pipe <4% in ncu). Exact for
// arbitrary inputs; no-hit conventions (lo=0, hi=full) match the reference.
// Rounds 6-8 established that fused-warp / regridded variants regress at the
// harness level despite equal ncu time — do not perturb this structure.

#define BB_H 512
#define BB_W 512
#define BB_THRESH 0.5f
#define FULLMASK 0xFFFFFFFFu

__global__ __launch_bounds__(128, 8)
void BoundingBox_2834678415682_kernel(const float* __restrict__ mask,
                                      float* __restrict__ out) {
    const int n    = blockIdx.x;
    const int wid  = threadIdx.x >> 5;   // 0..3 = direction
    const int lane = threadIdx.x & 31;
    const float* __restrict__ img = mask + (size_t)n * BB_H * BB_W;

    if (wid == 0) {
        // ymin: first row with any hit (default 0)
        int result = 0;
        for (int r = 0; r < BB_H; ++r) {
            bool rowhit = false;
            #pragma unroll 1
            for (int k = 0; k < BB_W / 32; ++k) {
                float v = img[(size_t)r * BB_W + k * 32 + lane];
                if (__ballot_sync(FULLMASK, v >= BB_THRESH)) { rowhit = true; break; }
            }
            if (rowhit) { result = r; break; }
        }
        if (lane == 0) out[n * 4 + 0] = (float)result;
    } else if (wid == 1) {
        // xmin: first column with any hit (default 0)
        int result = 0;
        for (int c = 0; c < BB_W; ++c) {
            bool colhit = false;
            #pragma unroll 1
            for (int k = 0; k < BB_H / 32; ++k) {
                float v = img[(size_t)(k * 32 + lane) * BB_W + c];
                if (__ballot_sync(FULLMASK, v >= BB_THRESH)) { colhit = true; break; }
            }
            if (colhit) { result = c; break; }
        }
        if (lane == 0) out[n * 4 + 1] = (float)result;
    } else if (wid == 2) {
        // ymax: last row with any hit, +1 (default H)
        int result = BB_H;
        for (int r = BB_H - 1; r >= 0; --r) {
            bool rowhit = false;
            #pragma unroll 1
            for (int k = 0; k < BB_W / 32; ++k) {
                float v = img[(size_t)r * BB_W + k * 32 + lane];
                if (__ballot_sync(FULLMASK, v >= BB_THRESH)) { rowhit = true; break; }
            }
            if (rowhit) { result = r + 1; break; }
        }
        if (result == 0) result = BB_H;   // unreachable (r=0 hit gives 1), kept for clarity
        if (lane == 0) out[n * 4 + 2] = (float)result;
    } else {
        // xmax: last column with any hit, +1 (default W)
        int result = BB_W;
        for (int c = BB_W - 1; c >= 0; --c) {
            bool colhit = false;
            #pragma unroll 1
            for (int k = 0; k < BB_H / 32; ++k) {
                float v = img[(size_t)(k * 32 + lane) * BB_W + c];
                if (__ballot_sync(FULLMASK, v >= BB_THRESH)) { colhit = true; break; }
            }
            if (colhit) { result = c + 1; break; }
        }
        if (lane == 0) out[n * 4 + 3] = (float)result;
    }
}

extern "C" void kernel_launch(void* const* d_in, const int* in_sizes, int n_in,
                              void* d_out, int out_size) {
    const float* mask = (const float*)d_in[0];
    float* out = (float*)d_out;

    const int N = in_sizes[0] / (BB_H * BB_W);

    BoundingBox_2834678415682_kernel<<<N, 128>>>(mask, out);
}

// round 11
// speedup vs baseline: 1.0047x; 1.0047x over previous
#include <cuda_runtime.h>
#include <cstdint>

// BoundingBox: mask [N,1,H,W] fp32 -> bbox [N,4] float32 (ymin, xmin, ymax, xmax),
// hit = (v >= 0.5f). Reference: lo = first hit, hi = last hit + 1; no hit -> (0, full).
//
// FINAL — verified best. This exact source has measured 4.544us (r5), 4.608us (r9),
// 6.912us (r10) at the harness with ncu kernel time stable at 4.3-4.5us; the harness
// split is bimodal measurement noise (same bits, both buckets), not code.
//
// The kernel sits on the hardware floor:
//   - ~5000cyc launch/ramp overhead + ONE scattered-line DRAM round trip
//     (32 lines, MLP=32) + drain; every ncu pipe <4% busy.
//   - Traffic 1.07MB vs 134MB input (126x cut via ballot-batched early-exit
//     edge scans: expected 1 batch per direction on dense random masks).
//   - Exact for arbitrary inputs; no-hit conventions (lo=0, hi=full) match the
//     reference. Fused-warp / regridded variants (r6-r8) were measured and do
//     not beat this structure.
//
// Structure: one block per image, 4 warps, one direction per warp, 32-element
// ballot-batched early-exit scans.

#define BB_H 512
#define BB_W 512
#define BB_THRESH 0.5f
#define FULLMASK 0xFFFFFFFFu

__global__ __launch_bounds__(128, 8)
void BoundingBox_2834678415682_kernel(const float* __restrict__ mask,
                                      float* __restrict__ out) {
    const int n    = blockIdx.x;
    const int wid  = threadIdx.x >> 5;   // 0..3 = direction
    const int lane = threadIdx.x & 31;
    const float* __restrict__ img = mask + (size_t)n * BB_H * BB_W;

    if (wid == 0) {
        // ymin: first row with any hit (default 0)
        int result = 0;
        for (int r = 0; r < BB_H; ++r) {
            bool rowhit = false;
            #pragma unroll 1
            for (int k = 0; k < BB_W / 32; ++k) {
                float v = img[(size_t)r * BB_W + k * 32 + lane];
                if (__ballot_sync(FULLMASK, v >= BB_THRESH)) { rowhit = true; break; }
            }
            if (rowhit) { result = r; break; }
        }
        if (lane == 0) out[n * 4 + 0] = (float)result;
    } else if (wid == 1) {
        // xmin: first column with any hit (default 0)
        int result = 0;
        for (int c = 0; c < BB_W; ++c) {
            bool colhit = false;
            #pragma unroll 1
            for (int k = 0; k < BB_H / 32; ++k) {
                float v = img[(size_t)(k * 32 + lane) * BB_W + c];
                if (__ballot_sync(FULLMASK, v >= BB_THRESH)) { colhit = true; break; }
            }
            if (colhit) { result = c; break; }
        }
        if (lane == 0) out[n * 4 + 1] = (float)result;
    } else if (wid == 2) {
        // ymax: last row with any hit, +1 (default H)
        int result = BB_H;
        for (int r = BB_H - 1; r >= 0; --r) {
            bool rowhit = false;
            #pragma unroll 1
            for (int k = 0; k < BB_W / 32; ++k) {
                float v = img[(size_t)r * BB_W + k * 32 + lane];
                if (__ballot_sync(FULLMASK, v >= BB_THRESH)) { rowhit = true; break; }
            }
            if (rowhit) { result = r + 1; break; }
        }
        if (result == 0) result = BB_H;   // unreachable (r=0 hit gives 1), kept for clarity
        if (lane == 0) out[n * 4 + 2] = (float)result;
    } else {
        // xmax: last column with any hit, +1 (default W)
        int result = BB_W;
        for (int c = BB_W - 1; c >= 0; --c) {
            bool colhit = false;
            #pragma unroll 1
            for (int k = 0; k < BB_H / 32; ++k) {
                float v = img[(size_t)(k * 32 + lane) * BB_W + c];
                if (__ballot_sync(FULLMASK, v >= BB_THRESH)) { colhit = true; break; }
            }
            if (colhit) { result = c + 1; break; }
        }
        if (lane == 0) out[n * 4 + 3] = (float)result;
    }
}

extern "C" void kernel_launch(void* const* d_in, const int* in_sizes, int n_in,
                              void* d_out, int out_size) {
    const float* mask = (const float*)d_in[0];
    float* out = (float*)d_out;

    const int N = in_sizes[0] / (BB_H * BB_W);

    BoundingBox_2834678415682_kernel<<<N, 128>>>(mask, out);
}

// round 12
// speedup vs baseline: 1.4897x; 1.4828x over previous
#include <cuda_runtime.h>
#include <cstdint>

// BoundingBox: mask [N,1,H,W] fp32 -> bbox [N,4] float32 (ymin, xmin, ymax, xmax),
// hit = (v >= 0.5f). Reference: lo = first hit, hi = last hit + 1; no hit -> (0, full).
//
// FINAL — verified best over 5 identical-source benches:
//   harness: {4.544, 4.608, 6.912, 6.880, 6.880} us  (bimodal DVFS/replay noise)
//   ncu:     {4.32, 4.16, 4.54, 4.32, 4.128} us      (true kernel time, at floor)
// Floor decomposition: ~5000cyc launch/ramp + ONE scattered-line DRAM round trip
// (32 lines, MLP=32) + drain; every pipe <4% busy. Traffic 1.07MB vs 134MB input
// (126x cut via ballot-batched early-exit edge scans; expected 1 batch/direction
// on dense random masks). Exact for arbitrary inputs; no-hit conventions
// (lo=0, hi=full) match the reference. Fused-warp / regridded variants (r6-r8)
// were measured and do not beat this structure — do not perturb.
//
// Structure: one block per image, 4 warps, one direction per warp, 32-element
// ballot-batched early-exit scans.

#define BB_H 512
#define BB_W 512
#define BB_THRESH 0.5f
#define FULLMASK 0xFFFFFFFFu

__global__ __launch_bounds__(128, 8)
void BoundingBox_2834678415682_kernel(const float* __restrict__ mask,
                                      float* __restrict__ out) {
    const int n    = blockIdx.x;
    const int wid  = threadIdx.x >> 5;   // 0..3 = direction
    const int lane = threadIdx.x & 31;
    const float* __restrict__ img = mask + (size_t)n * BB_H * BB_W;

    if (wid == 0) {
        // ymin: first row with any hit (default 0)
        int result = 0;
        for (int r = 0; r < BB_H; ++r) {
            bool rowhit = false;
            #pragma unroll 1
            for (int k = 0; k < BB_W / 32; ++k) {
                float v = img[(size_t)r * BB_W + k * 32 + lane];
                if (__ballot_sync(FULLMASK, v >= BB_THRESH)) { rowhit = true; break; }
            }
            if (rowhit) { result = r; break; }
        }
        if (lane == 0) out[n * 4 + 0] = (float)result;
    } else if (wid == 1) {
        // xmin: first column with any hit (default 0)
        int result = 0;
        for (int c = 0; c < BB_W; ++c) {
            bool colhit = false;
            #pragma unroll 1
            for (int k = 0; k < BB_H / 32; ++k) {
                float v = img[(size_t)(k * 32 + lane) * BB_W + c];
                if (__ballot_sync(FULLMASK, v >= BB_THRESH)) { colhit = true; break; }
            }
            if (colhit) { result = c; break; }
        }
        if (lane == 0) out[n * 4 + 1] = (float)result;
    } else if (wid == 2) {
        // ymax: last row with any hit, +1 (default H)
        int result = BB_H;
        for (int r = BB_H - 1; r >= 0; --r) {
            bool rowhit = false;
            #pragma unroll 1
            for (int k = 0; k < BB_W / 32; ++k) {
                float v = img[(size_t)r * BB_W + k * 32 + lane];
                if (__ballot_sync(FULLMASK, v >= BB_THRESH)) { rowhit = true; break; }
            }
            if (rowhit) { result = r + 1; break; }
        }
        if (result == 0) result = BB_H;   // unreachable (r=0 hit gives 1), kept for clarity
        if (lane == 0) out[n * 4 + 2] = (float)result;
    } else {
        // xmax: last column with any hit, +1 (default W)
        int result = BB_W;
        for (int c = BB_W - 1; c >= 0; --c) {
            bool colhit = false;
            #pragma unroll 1
            for (int k = 0; k < BB_H / 32; ++k) {
                float v = img[(size_t)(k * 32 + lane) * BB_W + c];
                if (__ballot_sync(FULLMASK, v >= BB_THRESH)) { colhit = true; break; }
            }
            if (colhit) { result = c + 1; break; }
        }
        if (lane == 0) out[n * 4 + 3] = (float)result;
    }
}

extern "C" void kernel_launch(void* const* d_in, const int* in_sizes, int n_in,
                              void* d_out, int out_size) {
    const float* mask = (const float*)d_in[0];
    float* out = (float*)d_out;

    const int N = in_sizes[0] / (BB_H * BB_W);

    BoundingBox_2834678415682_kernel<<<N, 128>>>(mask, out);
}